// round 14
// baseline (speedup 1.0000x reference)
#include <cuda_runtime.h>
#include <cuda_fp16.h>
#include <cstdint>

#define NB   4
#define CC   128
#define CR   64
#define HWS  4096
#define NJ   32            // j-tiles of 128
#define STAGE_BYTES 49152  // Kh 16K + Vh 32K
#define NSTAGE 3
#define PS   129           // tr stride (floats), odd -> <=2-way LDS conflicts

// ---------------------------------------------------------------------------
// Scratch
// ---------------------------------------------------------------------------
__device__ __half g_qh[NB * HWS * CR];
__device__ __half g_ql[NB * HWS * CR];
__device__ __half g_kh[NB * HWS * CR];
__device__ __half g_vh[NB * HWS * CC];
// proj_tc inputs
__device__ __half g_xh[NB * HWS * CC];   // x transposed [n][p][c], fp16 hi
__device__ __half g_xl[NB * HWS * CC];   // fp16 lo
__device__ __half g_wh[256 * 128];       // fused weights hi  [o][c]
__device__ __half g_wl[256 * 128];       // fused weights lo
__device__ float  g_bias[256];
__device__ float  g_alph[256];

// ---------------------------------------------------------------------------
// helpers
// ---------------------------------------------------------------------------
__device__ __forceinline__ uint32_t smem_u32(const void* p) {
    uint32_t a;
    asm("{ .reg .u64 t; cvta.to.shared.u64 t, %1; cvt.u32.u64 %0, t; }" : "=r"(a) : "l"(p));
    return a;
}
__device__ __forceinline__ uint32_t packh(float a, float b) {
    __half2 t = __floats2half2_rn(a, b);
    return *reinterpret_cast<uint32_t*>(&t);
}
__device__ __forceinline__ uint32_t ld32(const void* p) {
    return *reinterpret_cast<const uint32_t*>(p);
}
__device__ __forceinline__ void cpasync16(uint32_t dst, const void* src) {
    asm volatile("cp.async.cg.shared.global [%0], [%1], 16;" :: "r"(dst), "l"(src));
}
#define CP_COMMIT()   asm volatile("cp.async.commit_group;" ::: "memory")
#define CP_WAIT_ALL() asm volatile("cp.async.wait_group 0;" ::: "memory")

// mbarrier ops
#define MBAR_INIT(mb, c) asm volatile("mbarrier.init.shared.b64 [%0], %1;" :: "r"(mb), "r"(c) : "memory")
#define MBAR_ARRIVE(mb)  asm volatile("mbarrier.arrive.shared.b64 _, [%0];" :: "r"(mb) : "memory")
#define CPA_ARRIVE(mb)   asm volatile("cp.async.mbarrier.arrive.noinc.shared.b64 [%0];" :: "r"(mb) : "memory")

#define MBAR_WAIT(mb, ph) do {                                                   \
    uint32_t _m = (mb), _p = (uint32_t)(ph), _d;                                 \
    asm volatile("{ .reg .pred p; mbarrier.try_wait.parity.acquire.cta.shared::cta.b64 p, [%1], %2; selp.b32 %0,1,0,p; }" \
                 : "=r"(_d) : "r"(_m), "r"(_p) : "memory");                      \
    if (!_d) {                                                                   \
        asm volatile("{ .reg .pred P1; WL%=: mbarrier.try_wait.parity.acquire.cta.shared::cta.b64 P1, [%0], %1, 0x989680; @P1 bra.uni WD%=; bra.uni WL%=; WD%=: }" \
                     :: "r"(_m), "r"(_p) : "memory");                            \
    }                                                                            \
} while (0)

__device__ __forceinline__ void ldsm4(uint32_t& a, uint32_t& b, uint32_t& c, uint32_t& d, uint32_t addr) {
    asm volatile("ldmatrix.sync.aligned.m8n8.x4.shared.b16 {%0,%1,%2,%3}, [%4];"
                 : "=r"(a), "=r"(b), "=r"(c), "=r"(d) : "r"(addr));
}
__device__ __forceinline__ void ldsm4t(uint32_t& a, uint32_t& b, uint32_t& c, uint32_t& d, uint32_t addr) {
    asm volatile("ldmatrix.sync.aligned.m8n8.x4.trans.shared.b16 {%0,%1,%2,%3}, [%4];"
                 : "=r"(a), "=r"(b), "=r"(c), "=r"(d) : "r"(addr));
}
__device__ __forceinline__ void mma_f16(float* c, const uint32_t* a, uint32_t b0, uint32_t b1) {
    asm volatile("mma.sync.aligned.m16n8k16.row.col.f32.f16.f16.f32 "
                 "{%0,%1,%2,%3}, {%4,%5,%6,%7}, {%8,%9}, {%0,%1,%2,%3};"
                 : "+f"(c[0]), "+f"(c[1]), "+f"(c[2]), "+f"(c[3])
                 : "r"(a[0]), "r"(a[1]), "r"(a[2]), "r"(a[3]), "r"(b0), "r"(b1));
}

// ---------------------------------------------------------------------------
// Kernel X: transpose + hi/lo convert x: [n][c][p] f32 -> [n][p][c] fp16 x2
// ---------------------------------------------------------------------------
__global__ __launch_bounds__(256) void xconv_kernel(const float* __restrict__ x)
{
    __shared__ float t[32][33];
    const int n = blockIdx.z, c0 = blockIdx.y * 32, p0 = blockIdx.x * 32;
    const int tid = threadIdx.x;
#pragma unroll
    for (int i = 0; i < 4; ++i) {
        const int idx = tid + 256 * i;
        const int c_l = idx >> 5, p_l = idx & 31;
        t[c_l][p_l] = x[((size_t)(n * CC + c0 + c_l)) * HWS + p0 + p_l];
    }
    __syncthreads();
#pragma unroll
    for (int i = 0; i < 4; ++i) {
        const int idx = tid + 256 * i;
        const int p_l = idx >> 5, c_l = idx & 31;
        const float v = t[c_l][p_l];
        const float h = __half2float(__float2half_rn(v));
        const size_t off = ((size_t)(n * HWS + p0 + p_l)) * CC + c0 + c_l;
        g_xh[off] = __float2half_rn(h);
        g_xl[off] = __float2half_rn(v - h);
    }
}

// ---------------------------------------------------------------------------
// Kernel W: fuse w1/w2/wa -> hi/lo fp16 + bias/alpha.  grid 256 x 128thr.
// ---------------------------------------------------------------------------
__global__ __launch_bounds__(128) void wprep_kernel(
    const float* __restrict__ w1, const float* __restrict__ b1, const float* __restrict__ a1,
    const float* __restrict__ w2, const float* __restrict__ b2, const float* __restrict__ a2,
    const float* __restrict__ wa, const float* __restrict__ ba, const float* __restrict__ aa)
{
    const int o = blockIdx.x;
    const int c = threadIdx.x;
    const float* W; int oo; const float* bb; const float* ap;
    if (o < 64)        { W = w1; oo = o;       bb = b1; ap = a1; }
    else if (o < 128)  { W = w2; oo = o - 64;  bb = b2; ap = a2; }
    else               { W = wa; oo = o - 128; bb = ba; ap = aa; }
    const float v = W[oo * 128 + c];
    const float h = __half2float(__float2half_rn(v));
    g_wh[o * 128 + c] = __float2half_rn(h);
    g_wl[o * 128 + c] = __float2half_rn(v - h);
    if (c == 0) { g_bias[o] = bb[oo]; g_alph[o] = *ap; }
}

// ---------------------------------------------------------------------------
// Kernel C: tensor-core proj GEMM (3-pass hi/lo) + bias + PReLU -> scratch.
// CTA: 256 thr / 8 warps, output 256o x 128p.  grid (32, NB) = 1 wave.
// ---------------------------------------------------------------------------
__global__ __launch_bounds__(256, 1) void proj_tc(int dummy)
{
    extern __shared__ char smem[];
    const uint32_t sb = smem_u32(smem);
    const uint32_t WHs = sb, WLs = sb + 65536, XHs = sb + 131072, XLs = sb + 163840;

    const int n  = blockIdx.y;
    const int p0 = blockIdx.x * 128;
    const int tid = threadIdx.x;
    const int w = tid >> 5, lane = tid & 31;

    // ---- load W (hi/lo) and x tile (hi/lo) into swizzled smem ----
    {
        const char* wh = reinterpret_cast<const char*>(g_wh);
        const char* wl = reinterpret_cast<const char*>(g_wl);
        const char* xh = reinterpret_cast<const char*>(g_xh) + ((size_t)(n * HWS + p0)) * CC * 2;
        const char* xl = reinterpret_cast<const char*>(g_xl) + ((size_t)(n * HWS + p0)) * CC * 2;
#pragma unroll
        for (int r = 0; r < 16; ++r) {
            const int idx = tid + 256 * r;        // 0..4095
            const int o = idx >> 4, gq = idx & 15;
            const int dst = o * 256 + (((gq ^ (o & 7))) << 4);
            cpasync16(WHs + dst, wh + o * 256 + gq * 16);
            cpasync16(WLs + dst, wl + o * 256 + gq * 16);
        }
#pragma unroll
        for (int r = 0; r < 8; ++r) {
            const int idx = tid + 256 * r;        // 0..2047
            const int p = idx >> 4, gq = idx & 15;
            const int dst = p * 256 + (((gq ^ (p & 7))) << 4);
            cpasync16(XHs + dst, xh + p * 256 + gq * 16);
            cpasync16(XLs + dst, xl + p * 256 + gq * 16);
        }
    }
    CP_COMMIT();
    CP_WAIT_ALL();
    __syncthreads();

    // ---- GEMM: warp m32 x n128 over K=128, 3 passes (Wh*xh + Wh*xl + Wl*xh)
    float acc[2][16][4];
#pragma unroll
    for (int mh = 0; mh < 2; ++mh)
#pragma unroll
        for (int nc = 0; nc < 16; ++nc)
#pragma unroll
            for (int q = 0; q < 4; ++q) acc[mh][nc][q] = 0.f;

#pragma unroll
    for (int ks = 0; ks < 8; ++ks) {
        uint32_t ah[2][4], al[2][4];
#pragma unroll
        for (int mh = 0; mh < 2; ++mh) {
            const int row = w * 32 + mh * 16 + (lane & 15);
            const int gq = ks * 2 + (lane >> 4);
            const uint32_t ad = WHs + row * 256 + (((gq ^ (row & 7))) << 4);
            ldsm4(ah[mh][0], ah[mh][1], ah[mh][2], ah[mh][3], ad);
            ldsm4(al[mh][0], al[mh][1], al[mh][2], al[mh][3], ad + 65536);
        }
#pragma unroll
        for (int nc = 0; nc < 8; ++nc) {
            const int j = nc * 16 + ((lane >> 4) & 1) * 8 + (lane & 7);
            const int gq = ks * 2 + ((lane >> 3) & 1);
            const uint32_t ad = XHs + j * 256 + (((gq ^ (j & 7))) << 4);
            uint32_t b0, b1, b2, b3;
            ldsm4(b0, b1, b2, b3, ad);           // xh
            uint32_t c0, c1, c2, c3;
            ldsm4(c0, c1, c2, c3, ad + 32768);   // xl
#pragma unroll
            for (int mh = 0; mh < 2; ++mh) {
                mma_f16(acc[mh][2 * nc],     ah[mh], b0, b1);
                mma_f16(acc[mh][2 * nc + 1], ah[mh], b2, b3);
                mma_f16(acc[mh][2 * nc],     ah[mh], c0, c1);
                mma_f16(acc[mh][2 * nc + 1], ah[mh], c2, c3);
                mma_f16(acc[mh][2 * nc],     al[mh], b0, b1);
                mma_f16(acc[mh][2 * nc + 1], al[mh], b2, b3);
            }
        }
    }
    __syncthreads();   // done reading W/X smem

    // ---- bias + PReLU -> fp32 transpose buffer tr[o][PS] ----
    float* tr = reinterpret_cast<float*>(smem);
#pragma unroll
    for (int mh = 0; mh < 2; ++mh) {
        const int o1 = w * 32 + mh * 16 + (lane >> 2);
        const int o2 = o1 + 8;
        const float bi1 = g_bias[o1], al1 = g_alph[o1];
        const float bi2 = g_bias[o2], al2 = g_alph[o2];
#pragma unroll
        for (int t = 0; t < 16; ++t) {
            const int p = t * 8 + (lane & 3) * 2;
            float v0 = acc[mh][t][0] + bi1;
            float v1 = acc[mh][t][1] + bi1;
            float v2 = acc[mh][t][2] + bi2;
            float v3 = acc[mh][t][3] + bi2;
            v0 = (v0 >= 0.f) ? v0 : al1 * v0;
            v1 = (v1 >= 0.f) ? v1 : al1 * v1;
            v2 = (v2 >= 0.f) ? v2 : al2 * v2;
            v3 = (v3 >= 0.f) ? v3 : al2 * v3;
            tr[o1 * PS + p] = v0; tr[o1 * PS + p + 1] = v1;
            tr[o2 * PS + p] = v2; tr[o2 * PS + p + 1] = v3;
        }
    }
    __syncthreads();

    // ---- pack to scratch ----
#pragma unroll
    for (int r = 0; r < 16; ++r) {
        const int pair = tid + 256 * r;           // 0..4095
        const int p = pair >> 5, op = (pair & 31) * 2;
        const float v0 = tr[op * PS + p], v1 = tr[(op + 1) * PS + p];
        const float h0 = __half2float(__float2half_rn(v0));
        const float h1 = __half2float(__float2half_rn(v1));
        const size_t off = ((size_t)(n * HWS + p0 + p)) * CR + op;
        *reinterpret_cast<uint32_t*>(&g_qh[off]) = packh(h0, h1);
        *reinterpret_cast<uint32_t*>(&g_ql[off]) = packh(v0 - h0, v1 - h1);
    }
#pragma unroll
    for (int r = 0; r < 16; ++r) {
        const int pair = tid + 256 * r;
        const int p = pair >> 5, op = 64 + (pair & 31) * 2;
        const size_t off = ((size_t)(n * HWS + p0 + p)) * CR + op - 64;
        *reinterpret_cast<uint32_t*>(&g_kh[off]) =
            packh(tr[op * PS + p], tr[(op + 1) * PS + p]);
    }
#pragma unroll
    for (int r = 0; r < 32; ++r) {
        const int pair = tid + 256 * r;           // 0..8191
        const int p = pair >> 6, cp = pair & 63;
        const int op = 128 + cp * 2;
        const size_t off = ((size_t)(n * HWS + p0 + p)) * CC + cp * 2;
        *reinterpret_cast<uint32_t*>(&g_vh[off]) =
            packh(tr[op * PS + p], tr[(op + 1) * PS + p]);
    }
    (void)dummy;
}

// ---------------------------------------------------------------------------
// attn stage loader: Kh (16K) + V (32K) tiles, XOR-swizzled, via cp.async
// ---------------------------------------------------------------------------
__device__ __forceinline__ void load_tile(uint32_t stage, int n, int jt, int tid) {
    const char* kh = reinterpret_cast<const char*>(g_kh) + ((size_t)(n * HWS + jt * 128)) * CR * 2;
    const char* vh = reinterpret_cast<const char*>(g_vh) + ((size_t)(n * HWS + jt * 128)) * CC * 2;
#pragma unroll
    for (int r = 0; r < 4; ++r) {
        const int idx = tid + 256 * r;            // 0..1023
        const int j = idx >> 3, g = idx & 7;
        const int dstoff = j * 128 + (((g ^ (j & 7))) << 4);
        cpasync16(stage + dstoff, kh + j * 128 + g * 16);
    }
#pragma unroll
    for (int r = 0; r < 8; ++r) {
        const int idx = tid + 256 * r;            // 0..2047
        const int j = idx >> 4, g = idx & 15;
        const int dstoff = j * 256 + (((g ^ (j & 7))) << 4);
        cpasync16(stage + 16384 + dstoff, vh + j * 256 + g * 16);
    }
}

// ---------------------------------------------------------------------------
// Kernel 2: flash attention.  QK: A-side fp16 hi/lo 2-pass.  PV: fp16 1-pass
// FUSED with the exp/pack loop so MUFU hides under the HMMA stream.
// ---------------------------------------------------------------------------
__global__ __launch_bounds__(256, 1) void attn_hmma(float* __restrict__ out)
{
    extern __shared__ char smem[];
    const uint32_t sb  = smem_u32(smem);
    const uint32_t BAR = sb + NSTAGE * STAGE_BYTES;   // 6 mbarriers

    const int n   = blockIdx.y;
    const int i0  = blockIdx.x * 128;
    const int tid = threadIdx.x;
    const int w = tid >> 5, lane = tid & 31;
    const int g = lane >> 2, tig = lane & 3;
    const int r1 = w * 16 + g, r2 = r1 + 8;

    if (tid == 0) {
#pragma unroll
        for (int s = 0; s < NSTAGE; ++s) {
            MBAR_INIT(BAR + s * 8, 256);              // full[s]
            MBAR_INIT(BAR + 24 + s * 8, 256);         // empty[s]
        }
    }
    __syncthreads();

    // ---- Q fragments (persistent, fp16 hi/lo) ----
    uint32_t qh[4][4], ql[4][4];
    {
        const __half* q1h = g_qh + ((size_t)(n * HWS + i0 + r1)) * CR + tig * 2;
        const __half* q2h = g_qh + ((size_t)(n * HWS + i0 + r2)) * CR + tig * 2;
        const __half* q1l = g_ql + ((size_t)(n * HWS + i0 + r1)) * CR + tig * 2;
        const __half* q2l = g_ql + ((size_t)(n * HWS + i0 + r2)) * CR + tig * 2;
#pragma unroll
        for (int ks = 0; ks < 4; ++ks) {
            qh[ks][0] = ld32(q1h + ks * 16);     qh[ks][1] = ld32(q2h + ks * 16);
            qh[ks][2] = ld32(q1h + ks * 16 + 8); qh[ks][3] = ld32(q2h + ks * 16 + 8);
            ql[ks][0] = ld32(q1l + ks * 16);     ql[ks][1] = ld32(q2l + ks * 16);
            ql[ks][2] = ld32(q1l + ks * 16 + 8); ql[ks][3] = ld32(q2l + ks * 16 + 8);
        }
    }

    float m1 = -1e30f, m2 = -1e30f, l1 = 0.f, l2 = 0.f;

    float o[16][4];
#pragma unroll
    for (int cn = 0; cn < 16; ++cn)
#pragma unroll
        for (int q = 0; q < 4; ++q) o[cn][q] = 0.f;

    // prologue: stages 0 and 1
    load_tile(sb,               n, 0, tid);  CPA_ARRIVE(BAR);
    load_tile(sb + STAGE_BYTES, n, 1, tid);  CPA_ARRIVE(BAR + 8);

    int sc_ = 0, fpar = 0, fcnt = 0;     // consumer stage + full parity
    int sp_ = 2, epar = 0, ecnt = 0;     // producer stage + empty parity

    for (int jt = 0; jt < NJ; ++jt) {
        const int jt2 = jt + 2;
        if (jt2 < NJ) {
            if (jt2 >= NSTAGE) {
                MBAR_WAIT(BAR + 24 + sp_ * 8, epar);
                if (++ecnt == NSTAGE) { ecnt = 0; epar ^= 1; }
            }
            load_tile(sb + sp_ * STAGE_BYTES, n, jt2, tid);
            CPA_ARRIVE(BAR + sp_ * 8);
            if (++sp_ == NSTAGE) sp_ = 0;
        }

        MBAR_WAIT(BAR + sc_ * 8, fpar);
        if (++fcnt == NSTAGE) { fcnt = 0; fpar ^= 1; }

        const uint32_t KHs = sb + sc_ * STAGE_BYTES;
        const uint32_t VHs = KHs + 16384;

        // ---- QK: S = (Qh + Ql) * Kh  (fp16 A-split 2-pass, exact in Q) ----
        float s[16][4];
#pragma unroll
        for (int jn = 0; jn < 16; ++jn)
#pragma unroll
            for (int q = 0; q < 4; ++q) s[jn][q] = 0.f;

#pragma unroll
        for (int ks = 0; ks < 4; ++ks) {
#pragma unroll
            for (int jnp = 0; jnp < 8; ++jnp) {
                const int j = jnp * 16 + ((lane >> 4) & 1) * 8 + (lane & 7);
                const int gr = ks * 2 + ((lane >> 3) & 1);
                const uint32_t ad = KHs + j * 128 + (((gr) ^ (j & 7)) << 4);
                uint32_t b0, b1, b2, b3;
                ldsm4(b0, b1, b2, b3, ad);
                mma_f16(s[2 * jnp],     qh[ks], b0, b1);
                mma_f16(s[2 * jnp + 1], qh[ks], b2, b3);
                mma_f16(s[2 * jnp],     ql[ks], b0, b1);
                mma_f16(s[2 * jnp + 1], ql[ks], b2, b3);
            }
        }

        // ---- online softmax: true row max (quad-reduced), rescale O ----
        float mx1 = -1e30f, mx2 = -1e30f;
#pragma unroll
        for (int jn = 0; jn < 16; ++jn) {
            mx1 = fmaxf(mx1, fmaxf(s[jn][0], s[jn][1]));
            mx2 = fmaxf(mx2, fmaxf(s[jn][2], s[jn][3]));
        }
        mx1 = fmaxf(mx1, __shfl_xor_sync(0xffffffffu, mx1, 1));
        mx1 = fmaxf(mx1, __shfl_xor_sync(0xffffffffu, mx1, 2));
        mx2 = fmaxf(mx2, __shfl_xor_sync(0xffffffffu, mx2, 1));
        mx2 = fmaxf(mx2, __shfl_xor_sync(0xffffffffu, mx2, 2));
        const float mn1 = fmaxf(m1, mx1), mn2 = fmaxf(m2, mx2);
        const float sc1 = __expf(m1 - mn1), sc2 = __expf(m2 - mn2);
        m1 = mn1; m2 = mn2;
        l1 *= sc1; l2 *= sc2;
#pragma unroll
        for (int cn = 0; cn < 16; ++cn) {
            o[cn][0] *= sc1; o[cn][1] *= sc1;
            o[cn][2] *= sc2; o[cn][3] *= sc2;
        }

        // ---- FUSED exp/pack + PV: per 16-j slab, exps feed straight into
        //      that slab's HMMAs so MUFU overlaps the tensor stream ----
#pragma unroll
        for (int t = 0; t < 8; ++t) {
            const float p0 = __expf(s[2 * t][0] - mn1);
            const float p1 = __expf(s[2 * t][1] - mn1);
            const float p2 = __expf(s[2 * t][2] - mn2);
            const float p3 = __expf(s[2 * t][3] - mn2);
            const float p4 = __expf(s[2 * t + 1][0] - mn1);
            const float p5 = __expf(s[2 * t + 1][1] - mn1);
            const float p6 = __expf(s[2 * t + 1][2] - mn2);
            const float p7 = __expf(s[2 * t + 1][3] - mn2);
            l1 += p0 + p1;
            l2 += p2 + p3;
            l1 += p4 + p5;
            l2 += p6 + p7;
            const uint32_t a[4] = {packh(p0, p1), packh(p2, p3),
                                   packh(p4, p5), packh(p6, p7)};
#pragma unroll
            for (int cnp = 0; cnp < 8; ++cnp) {
                const int j = t * 16 + ((lane >> 3) & 1) * 8 + (lane & 7);
                const int gr = cnp * 2 + ((lane >> 4) & 1);
                const uint32_t ad = VHs + j * 256 + (((gr) ^ (j & 7)) << 4);
                uint32_t b0, b1, b2, b3;
                ldsm4t(b0, b1, b2, b3, ad);
                mma_f16(o[2 * cnp],     a, b0, b1);
                mma_f16(o[2 * cnp + 1], a, b2, b3);
            }
        }

        MBAR_ARRIVE(BAR + 24 + sc_ * 8);
        if (++sc_ == NSTAGE) sc_ = 0;
    }

    __syncthreads();   // all warps done before tr reuses stage 0

    // ---- epilogue: reduce l over quad, normalize, transpose, store ----
    l1 += __shfl_xor_sync(0xffffffffu, l1, 1);
    l1 += __shfl_xor_sync(0xffffffffu, l1, 2);
    l2 += __shfl_xor_sync(0xffffffffu, l2, 1);
    l2 += __shfl_xor_sync(0xffffffffu, l2, 2);
    const float inv1 = 1.f / l1;
    const float inv2 = 1.f / l2;

    float* tr = reinterpret_cast<float*>(smem);    // [c][i] 64KB
#pragma unroll
    for (int cn = 0; cn < 16; ++cn) {
        const int c = cn * 8 + tig * 2;
        tr[c * 128 + r1]       = o[cn][0] * inv1;
        tr[(c + 1) * 128 + r1] = o[cn][1] * inv1;
        tr[c * 128 + r2]       = o[cn][2] * inv2;
        tr[(c + 1) * 128 + r2] = o[cn][3] * inv2;
    }
    __syncthreads();

#pragma unroll
    for (int rep = 0; rep < 16; ++rep) {
        const int lin = rep * 256 + tid;
        const int c = lin >> 5, i4 = (lin & 31) * 4;
        const float4 f = *reinterpret_cast<const float4*>(&tr[c * 128 + i4]);
        *reinterpret_cast<float4*>(&out[((size_t)n * CC + c) * HWS + i0 + i4]) = f;
    }
}

// ---------------------------------------------------------------------------
extern "C" void kernel_launch(void* const* d_in, const int* in_sizes, int n_in,
                              void* d_out, int out_size)
{
    (void)in_sizes; (void)n_in; (void)out_size;
    const float* x  = (const float*)d_in[0];
    const float* w1 = (const float*)d_in[1];
    const float* b1 = (const float*)d_in[2];
    const float* a1 = (const float*)d_in[3];
    const float* w2 = (const float*)d_in[4];
    const float* b2 = (const float*)d_in[5];
    const float* a2 = (const float*)d_in[6];
    const float* wa = (const float*)d_in[7];
    const float* ba = (const float*)d_in[8];
    const float* aa = (const float*)d_in[9];
    float* out = (float*)d_out;

    wprep_kernel<<<256, 128>>>(w1, b1, a1, w2, b2, a2, wa, ba, aa);
    xconv_kernel<<<dim3(HWS / 32, CC / 32, NB), 256>>>(x);

    const int smem1 = 196608;   // 192 KB
    cudaFuncSetAttribute(proj_tc, cudaFuncAttributeMaxDynamicSharedMemorySize, smem1);
    proj_tc<<<dim3(HWS / 128, NB), 256, smem1>>>(0);

    const int smem2 = NSTAGE * STAGE_BYTES + 64;   // 144 KB + barriers
    cudaFuncSetAttribute(attn_hmma, cudaFuncAttributeMaxDynamicSharedMemorySize, smem2);
    attn_hmma<<<dim3(HWS / 128, NB), 256, smem2>>>(out);
}

// round 15
// speedup vs baseline: 1.0200x; 1.0200x over previous
#include <cuda_runtime.h>
#include <cuda_fp16.h>
#include <cstdint>

#define NB   4
#define CC   128
#define CR   64
#define HWS  4096
#define NJ   32            // j-tiles of 128
#define STAGE_BYTES 49152  // Kh 16K + Vh 32K
#define NSTAGE 3
#define PS   129           // tr stride (floats), odd -> <=2-way LDS conflicts

// ---------------------------------------------------------------------------
// Scratch
// ---------------------------------------------------------------------------
__device__ __half g_qh[NB * HWS * CR];
__device__ __half g_ql[NB * HWS * CR];
__device__ __half g_kh[NB * HWS * CR];
__device__ __half g_vh[NB * HWS * CC];
// proj_tc inputs
__device__ __half g_xh[NB * HWS * CC];   // x transposed [n][p][c], fp16 hi
__device__ __half g_xl[NB * HWS * CC];   // fp16 lo
__device__ __half g_wh[256 * 128];       // fused weights hi  [o][c]
__device__ __half g_wl[256 * 128];       // fused weights lo
__device__ float  g_bias[256];
__device__ float  g_alph[256];

// ---------------------------------------------------------------------------
// helpers
// ---------------------------------------------------------------------------
__device__ __forceinline__ uint32_t smem_u32(const void* p) {
    uint32_t a;
    asm("{ .reg .u64 t; cvta.to.shared.u64 t, %1; cvt.u32.u64 %0, t; }" : "=r"(a) : "l"(p));
    return a;
}
__device__ __forceinline__ uint32_t packh(float a, float b) {
    __half2 t = __floats2half2_rn(a, b);
    return *reinterpret_cast<uint32_t*>(&t);
}
__device__ __forceinline__ uint32_t ld32(const void* p) {
    return *reinterpret_cast<const uint32_t*>(p);
}
__device__ __forceinline__ void cpasync16(uint32_t dst, const void* src) {
    asm volatile("cp.async.cg.shared.global [%0], [%1], 16;" :: "r"(dst), "l"(src));
}
#define CP_COMMIT()   asm volatile("cp.async.commit_group;" ::: "memory")
#define CP_WAIT_ALL() asm volatile("cp.async.wait_group 0;" ::: "memory")

// mbarrier ops
#define MBAR_INIT(mb, c) asm volatile("mbarrier.init.shared.b64 [%0], %1;" :: "r"(mb), "r"(c) : "memory")
#define MBAR_ARRIVE(mb)  asm volatile("mbarrier.arrive.shared.b64 _, [%0];" :: "r"(mb) : "memory")
#define CPA_ARRIVE(mb)   asm volatile("cp.async.mbarrier.arrive.noinc.shared.b64 [%0];" :: "r"(mb) : "memory")

#define MBAR_WAIT(mb, ph) do {                                                   \
    uint32_t _m = (mb), _p = (uint32_t)(ph), _d;                                 \
    asm volatile("{ .reg .pred p; mbarrier.try_wait.parity.acquire.cta.shared::cta.b64 p, [%1], %2; selp.b32 %0,1,0,p; }" \
                 : "=r"(_d) : "r"(_m), "r"(_p) : "memory");                      \
    if (!_d) {                                                                   \
        asm volatile("{ .reg .pred P1; WL%=: mbarrier.try_wait.parity.acquire.cta.shared::cta.b64 P1, [%0], %1, 0x989680; @P1 bra.uni WD%=; bra.uni WL%=; WD%=: }" \
                     :: "r"(_m), "r"(_p) : "memory");                            \
    }                                                                            \
} while (0)

__device__ __forceinline__ void ldsm4(uint32_t& a, uint32_t& b, uint32_t& c, uint32_t& d, uint32_t addr) {
    asm volatile("ldmatrix.sync.aligned.m8n8.x4.shared.b16 {%0,%1,%2,%3}, [%4];"
                 : "=r"(a), "=r"(b), "=r"(c), "=r"(d) : "r"(addr));
}
__device__ __forceinline__ void ldsm4t(uint32_t& a, uint32_t& b, uint32_t& c, uint32_t& d, uint32_t addr) {
    asm volatile("ldmatrix.sync.aligned.m8n8.x4.trans.shared.b16 {%0,%1,%2,%3}, [%4];"
                 : "=r"(a), "=r"(b), "=r"(c), "=r"(d) : "r"(addr));
}
__device__ __forceinline__ void mma_f16(float* c, const uint32_t* a, uint32_t b0, uint32_t b1) {
    asm volatile("mma.sync.aligned.m16n8k16.row.col.f32.f16.f16.f32 "
                 "{%0,%1,%2,%3}, {%4,%5,%6,%7}, {%8,%9}, {%0,%1,%2,%3};"
                 : "+f"(c[0]), "+f"(c[1]), "+f"(c[2]), "+f"(c[3])
                 : "r"(a[0]), "r"(a[1]), "r"(a[2]), "r"(a[3]), "r"(b0), "r"(b1));
}

// ---------------------------------------------------------------------------
// Kernel P: fused prep.
//  - all blocks: transpose + hi/lo convert x [n][c][p] f32 -> [n][p][c] fp16x2
//  - blocks with (y==0, z==0) additionally convert one (o,c) weight element
//    per thread (128 blocks x 256 thr == 256 o x 128 c) + bias/alpha.
// ---------------------------------------------------------------------------
__global__ __launch_bounds__(256) void prep_kernel(
    const float* __restrict__ x,
    const float* __restrict__ w1, const float* __restrict__ b1, const float* __restrict__ a1,
    const float* __restrict__ w2, const float* __restrict__ b2, const float* __restrict__ a2,
    const float* __restrict__ wa, const float* __restrict__ ba, const float* __restrict__ aa)
{
    __shared__ float t[32][33];
    const int n = blockIdx.z, c0 = blockIdx.y * 32, p0 = blockIdx.x * 32;
    const int tid = threadIdx.x;

    // ---- piggybacked weight prep (exactly covers 256o x 128c) ----
    if (blockIdx.y == 0 && blockIdx.z == 0) {
        const int idx = blockIdx.x * 256 + tid;   // 0..32767
        const int o = idx >> 7, c = idx & 127;
        const float* W; int oo; const float* bb; const float* ap;
        if (o < 64)        { W = w1; oo = o;       bb = b1; ap = a1; }
        else if (o < 128)  { W = w2; oo = o - 64;  bb = b2; ap = a2; }
        else               { W = wa; oo = o - 128; bb = ba; ap = aa; }
        const float v = W[oo * 128 + c];
        const float h = __half2float(__float2half_rn(v));
        g_wh[o * 128 + c] = __float2half_rn(h);
        g_wl[o * 128 + c] = __float2half_rn(v - h);
        if (c == 0) { g_bias[o] = bb[oo]; g_alph[o] = *ap; }
    }

    // ---- x transpose/convert ----
#pragma unroll
    for (int i = 0; i < 4; ++i) {
        const int idx = tid + 256 * i;
        const int c_l = idx >> 5, p_l = idx & 31;
        t[c_l][p_l] = x[((size_t)(n * CC + c0 + c_l)) * HWS + p0 + p_l];
    }
    __syncthreads();
#pragma unroll
    for (int i = 0; i < 4; ++i) {
        const int idx = tid + 256 * i;
        const int p_l = idx >> 5, c_l = idx & 31;
        const float v = t[c_l][p_l];
        const float h = __half2float(__float2half_rn(v));
        const size_t off = ((size_t)(n * HWS + p0 + p_l)) * CC + c0 + c_l;
        g_xh[off] = __float2half_rn(h);
        g_xl[off] = __float2half_rn(v - h);
    }
}

// ---------------------------------------------------------------------------
// Kernel C: tensor-core proj GEMM (3-pass hi/lo) + bias + PReLU -> scratch.
// CTA: 256 thr / 8 warps, output 256o x 128p.  grid (32, NB) = 1 wave.
// ---------------------------------------------------------------------------
__global__ __launch_bounds__(256, 1) void proj_tc(int dummy)
{
    extern __shared__ char smem[];
    const uint32_t sb = smem_u32(smem);
    const uint32_t WHs = sb, WLs = sb + 65536, XHs = sb + 131072, XLs = sb + 163840;

    const int n  = blockIdx.y;
    const int p0 = blockIdx.x * 128;
    const int tid = threadIdx.x;
    const int w = tid >> 5, lane = tid & 31;

    // ---- load W (hi/lo) and x tile (hi/lo) into swizzled smem ----
    {
        const char* wh = reinterpret_cast<const char*>(g_wh);
        const char* wl = reinterpret_cast<const char*>(g_wl);
        const char* xh = reinterpret_cast<const char*>(g_xh) + ((size_t)(n * HWS + p0)) * CC * 2;
        const char* xl = reinterpret_cast<const char*>(g_xl) + ((size_t)(n * HWS + p0)) * CC * 2;
#pragma unroll
        for (int r = 0; r < 16; ++r) {
            const int idx = tid + 256 * r;        // 0..4095
            const int o = idx >> 4, gq = idx & 15;
            const int dst = o * 256 + (((gq ^ (o & 7))) << 4);
            cpasync16(WHs + dst, wh + o * 256 + gq * 16);
            cpasync16(WLs + dst, wl + o * 256 + gq * 16);
        }
#pragma unroll
        for (int r = 0; r < 8; ++r) {
            const int idx = tid + 256 * r;        // 0..2047
            const int p = idx >> 4, gq = idx & 15;
            const int dst = p * 256 + (((gq ^ (p & 7))) << 4);
            cpasync16(XHs + dst, xh + p * 256 + gq * 16);
            cpasync16(XLs + dst, xl + p * 256 + gq * 16);
        }
    }
    CP_COMMIT();
    CP_WAIT_ALL();
    __syncthreads();

    // ---- GEMM: warp m32 x n128 over K=128, 3 passes (Wh*xh + Wh*xl + Wl*xh)
    float acc[2][16][4];
#pragma unroll
    for (int mh = 0; mh < 2; ++mh)
#pragma unroll
        for (int nc = 0; nc < 16; ++nc)
#pragma unroll
            for (int q = 0; q < 4; ++q) acc[mh][nc][q] = 0.f;

#pragma unroll
    for (int ks = 0; ks < 8; ++ks) {
        uint32_t ah[2][4], al[2][4];
#pragma unroll
        for (int mh = 0; mh < 2; ++mh) {
            const int row = w * 32 + mh * 16 + (lane & 15);
            const int gq = ks * 2 + (lane >> 4);
            const uint32_t ad = WHs + row * 256 + (((gq ^ (row & 7))) << 4);
            ldsm4(ah[mh][0], ah[mh][1], ah[mh][2], ah[mh][3], ad);
            ldsm4(al[mh][0], al[mh][1], al[mh][2], al[mh][3], ad + 65536);
        }
#pragma unroll
        for (int nc = 0; nc < 8; ++nc) {
            const int j = nc * 16 + ((lane >> 4) & 1) * 8 + (lane & 7);
            const int gq = ks * 2 + ((lane >> 3) & 1);
            const uint32_t ad = XHs + j * 256 + (((gq ^ (j & 7))) << 4);
            uint32_t b0, b1, b2, b3;
            ldsm4(b0, b1, b2, b3, ad);           // xh
            uint32_t c0, c1, c2, c3;
            ldsm4(c0, c1, c2, c3, ad + 32768);   // xl
#pragma unroll
            for (int mh = 0; mh < 2; ++mh) {
                mma_f16(acc[mh][2 * nc],     ah[mh], b0, b1);
                mma_f16(acc[mh][2 * nc + 1], ah[mh], b2, b3);
                mma_f16(acc[mh][2 * nc],     ah[mh], c0, c1);
                mma_f16(acc[mh][2 * nc + 1], ah[mh], c2, c3);
                mma_f16(acc[mh][2 * nc],     al[mh], b0, b1);
                mma_f16(acc[mh][2 * nc + 1], al[mh], b2, b3);
            }
        }
    }
    __syncthreads();   // done reading W/X smem

    // ---- bias + PReLU -> fp32 transpose buffer tr[o][PS] ----
    float* tr = reinterpret_cast<float*>(smem);
#pragma unroll
    for (int mh = 0; mh < 2; ++mh) {
        const int o1 = w * 32 + mh * 16 + (lane >> 2);
        const int o2 = o1 + 8;
        const float bi1 = g_bias[o1], al1 = g_alph[o1];
        const float bi2 = g_bias[o2], al2 = g_alph[o2];
#pragma unroll
        for (int t = 0; t < 16; ++t) {
            const int p = t * 8 + (lane & 3) * 2;
            float v0 = acc[mh][t][0] + bi1;
            float v1 = acc[mh][t][1] + bi1;
            float v2 = acc[mh][t][2] + bi2;
            float v3 = acc[mh][t][3] + bi2;
            v0 = (v0 >= 0.f) ? v0 : al1 * v0;
            v1 = (v1 >= 0.f) ? v1 : al1 * v1;
            v2 = (v2 >= 0.f) ? v2 : al2 * v2;
            v3 = (v3 >= 0.f) ? v3 : al2 * v3;
            tr[o1 * PS + p] = v0; tr[o1 * PS + p + 1] = v1;
            tr[o2 * PS + p] = v2; tr[o2 * PS + p + 1] = v3;
        }
    }
    __syncthreads();

    // ---- pack to scratch ----
#pragma unroll
    for (int r = 0; r < 16; ++r) {
        const int pair = tid + 256 * r;           // 0..4095
        const int p = pair >> 5, op = (pair & 31) * 2;
        const float v0 = tr[op * PS + p], v1 = tr[(op + 1) * PS + p];
        const float h0 = __half2float(__float2half_rn(v0));
        const float h1 = __half2float(__float2half_rn(v1));
        const size_t off = ((size_t)(n * HWS + p0 + p)) * CR + op;
        *reinterpret_cast<uint32_t*>(&g_qh[off]) = packh(h0, h1);
        *reinterpret_cast<uint32_t*>(&g_ql[off]) = packh(v0 - h0, v1 - h1);
    }
#pragma unroll
    for (int r = 0; r < 16; ++r) {
        const int pair = tid + 256 * r;
        const int p = pair >> 5, op = 64 + (pair & 31) * 2;
        const size_t off = ((size_t)(n * HWS + p0 + p)) * CR + op - 64;
        *reinterpret_cast<uint32_t*>(&g_kh[off]) =
            packh(tr[op * PS + p], tr[(op + 1) * PS + p]);
    }
#pragma unroll
    for (int r = 0; r < 32; ++r) {
        const int pair = tid + 256 * r;           // 0..8191
        const int p = pair >> 6, cp = pair & 63;
        const int op = 128 + cp * 2;
        const size_t off = ((size_t)(n * HWS + p0 + p)) * CC + cp * 2;
        *reinterpret_cast<uint32_t*>(&g_vh[off]) =
            packh(tr[op * PS + p], tr[(op + 1) * PS + p]);
    }
    (void)dummy;
}

// ---------------------------------------------------------------------------
// attn stage loader: Kh (16K) + V (32K) tiles, XOR-swizzled, via cp.async
// ---------------------------------------------------------------------------
__device__ __forceinline__ void load_tile(uint32_t stage, int n, int jt, int tid) {
    const char* kh = reinterpret_cast<const char*>(g_kh) + ((size_t)(n * HWS + jt * 128)) * CR * 2;
    const char* vh = reinterpret_cast<const char*>(g_vh) + ((size_t)(n * HWS + jt * 128)) * CC * 2;
#pragma unroll
    for (int r = 0; r < 4; ++r) {
        const int idx = tid + 256 * r;            // 0..1023
        const int j = idx >> 3, g = idx & 7;
        const int dstoff = j * 128 + (((g ^ (j & 7))) << 4);
        cpasync16(stage + dstoff, kh + j * 128 + g * 16);
    }
#pragma unroll
    for (int r = 0; r < 8; ++r) {
        const int idx = tid + 256 * r;            // 0..2047
        const int j = idx >> 4, g = idx & 15;
        const int dstoff = j * 256 + (((g ^ (j & 7))) << 4);
        cpasync16(stage + 16384 + dstoff, vh + j * 256 + g * 16);
    }
}

// ---------------------------------------------------------------------------
// Kernel 2: flash attention (R13-exact body, best measured: 112.4us).
// QK: A-side fp16 hi/lo 2-pass (exact Q), K single fp16.  PV: fp16 1-pass.
// ---------------------------------------------------------------------------
__global__ __launch_bounds__(256, 1) void attn_hmma(float* __restrict__ out)
{
    extern __shared__ char smem[];
    const uint32_t sb  = smem_u32(smem);
    const uint32_t BAR = sb + NSTAGE * STAGE_BYTES;   // 6 mbarriers

    const int n   = blockIdx.y;
    const int i0  = blockIdx.x * 128;
    const int tid = threadIdx.x;
    const int w = tid >> 5, lane = tid & 31;
    const int g = lane >> 2, tig = lane & 3;
    const int r1 = w * 16 + g, r2 = r1 + 8;

    if (tid == 0) {
#pragma unroll
        for (int s = 0; s < NSTAGE; ++s) {
            MBAR_INIT(BAR + s * 8, 256);              // full[s]
            MBAR_INIT(BAR + 24 + s * 8, 256);         // empty[s]
        }
    }
    __syncthreads();

    // ---- Q fragments (persistent, fp16 hi/lo) ----
    uint32_t qh[4][4], ql[4][4];
    {
        const __half* q1h = g_qh + ((size_t)(n * HWS + i0 + r1)) * CR + tig * 2;
        const __half* q2h = g_qh + ((size_t)(n * HWS + i0 + r2)) * CR + tig * 2;
        const __half* q1l = g_ql + ((size_t)(n * HWS + i0 + r1)) * CR + tig * 2;
        const __half* q2l = g_ql + ((size_t)(n * HWS + i0 + r2)) * CR + tig * 2;
#pragma unroll
        for (int ks = 0; ks < 4; ++ks) {
            qh[ks][0] = ld32(q1h + ks * 16);     qh[ks][1] = ld32(q2h + ks * 16);
            qh[ks][2] = ld32(q1h + ks * 16 + 8); qh[ks][3] = ld32(q2h + ks * 16 + 8);
            ql[ks][0] = ld32(q1l + ks * 16);     ql[ks][1] = ld32(q2l + ks * 16);
            ql[ks][2] = ld32(q1l + ks * 16 + 8); ql[ks][3] = ld32(q2l + ks * 16 + 8);
        }
    }

    float m1 = -1e30f, m2 = -1e30f, l1 = 0.f, l2 = 0.f;

    float o[16][4];
#pragma unroll
    for (int cn = 0; cn < 16; ++cn)
#pragma unroll
        for (int q = 0; q < 4; ++q) o[cn][q] = 0.f;

    // prologue: stages 0 and 1
    load_tile(sb,               n, 0, tid);  CPA_ARRIVE(BAR);
    load_tile(sb + STAGE_BYTES, n, 1, tid);  CPA_ARRIVE(BAR + 8);

    int sc_ = 0, fpar = 0, fcnt = 0;     // consumer stage + full parity
    int sp_ = 2, epar = 0, ecnt = 0;     // producer stage + empty parity

    for (int jt = 0; jt < NJ; ++jt) {
        const int jt2 = jt + 2;
        if (jt2 < NJ) {
            if (jt2 >= NSTAGE) {
                MBAR_WAIT(BAR + 24 + sp_ * 8, epar);
                if (++ecnt == NSTAGE) { ecnt = 0; epar ^= 1; }
            }
            load_tile(sb + sp_ * STAGE_BYTES, n, jt2, tid);
            CPA_ARRIVE(BAR + sp_ * 8);
            if (++sp_ == NSTAGE) sp_ = 0;
        }

        MBAR_WAIT(BAR + sc_ * 8, fpar);
        if (++fcnt == NSTAGE) { fcnt = 0; fpar ^= 1; }

        const uint32_t KHs = sb + sc_ * STAGE_BYTES;
        const uint32_t VHs = KHs + 16384;

        // ---- QK: S = (Qh + Ql) * Kh  (fp16 A-split 2-pass, exact in Q) ----
        float s[16][4];
#pragma unroll
        for (int jn = 0; jn < 16; ++jn)
#pragma unroll
            for (int q = 0; q < 4; ++q) s[jn][q] = 0.f;

#pragma unroll
        for (int ks = 0; ks < 4; ++ks) {
#pragma unroll
            for (int jnp = 0; jnp < 8; ++jnp) {
                const int j = jnp * 16 + ((lane >> 4) & 1) * 8 + (lane & 7);
                const int gr = ks * 2 + ((lane >> 3) & 1);
                const uint32_t ad = KHs + j * 128 + (((gr) ^ (j & 7)) << 4);
                uint32_t b0, b1, b2, b3;
                ldsm4(b0, b1, b2, b3, ad);
                mma_f16(s[2 * jnp],     qh[ks], b0, b1);
                mma_f16(s[2 * jnp + 1], qh[ks], b2, b3);
                mma_f16(s[2 * jnp],     ql[ks], b0, b1);
                mma_f16(s[2 * jnp + 1], ql[ks], b2, b3);
            }
        }

        // ---- online softmax: true row max (quad-reduced), rescale O ----
        float mx1 = -1e30f, mx2 = -1e30f;
#pragma unroll
        for (int jn = 0; jn < 16; ++jn) {
            mx1 = fmaxf(mx1, fmaxf(s[jn][0], s[jn][1]));
            mx2 = fmaxf(mx2, fmaxf(s[jn][2], s[jn][3]));
        }
        mx1 = fmaxf(mx1, __shfl_xor_sync(0xffffffffu, mx1, 1));
        mx1 = fmaxf(mx1, __shfl_xor_sync(0xffffffffu, mx1, 2));
        mx2 = fmaxf(mx2, __shfl_xor_sync(0xffffffffu, mx2, 1));
        mx2 = fmaxf(mx2, __shfl_xor_sync(0xffffffffu, mx2, 2));
        const float mn1 = fmaxf(m1, mx1), mn2 = fmaxf(m2, mx2);
        const float sc1 = __expf(m1 - mn1), sc2 = __expf(m2 - mn2);
        m1 = mn1; m2 = mn2;
        l1 *= sc1; l2 *= sc2;
#pragma unroll
        for (int cn = 0; cn < 16; ++cn) {
            o[cn][0] *= sc1; o[cn][1] *= sc1;
            o[cn][2] *= sc2; o[cn][3] *= sc2;
        }

        uint32_t ph[16][2];
#pragma unroll
        for (int jn = 0; jn < 16; ++jn) {
            const float p0 = __expf(s[jn][0] - mn1);
            const float p1 = __expf(s[jn][1] - mn1);
            const float p2 = __expf(s[jn][2] - mn2);
            const float p3 = __expf(s[jn][3] - mn2);
            l1 += p0 + p1;
            l2 += p2 + p3;
            ph[jn][0] = packh(p0, p1);
            ph[jn][1] = packh(p2, p3);
        }

        // ---- PV: O += P*V (single fp16 pass) ----
#pragma unroll
        for (int t = 0; t < 8; ++t) {
            const uint32_t a[4] = {ph[2 * t][0], ph[2 * t][1], ph[2 * t + 1][0], ph[2 * t + 1][1]};
#pragma unroll
            for (int cnp = 0; cnp < 8; ++cnp) {
                const int j = t * 16 + ((lane >> 3) & 1) * 8 + (lane & 7);
                const int gr = cnp * 2 + ((lane >> 4) & 1);
                const uint32_t ad = VHs + j * 256 + (((gr) ^ (j & 7)) << 4);
                uint32_t b0, b1, b2, b3;
                ldsm4t(b0, b1, b2, b3, ad);
                mma_f16(o[2 * cnp],     a, b0, b1);
                mma_f16(o[2 * cnp + 1], a, b2, b3);
            }
        }

        MBAR_ARRIVE(BAR + 24 + sc_ * 8);
        if (++sc_ == NSTAGE) sc_ = 0;
    }

    __syncthreads();   // all warps done before tr reuses stage 0

    // ---- epilogue: reduce l over quad, normalize, transpose, store ----
    l1 += __shfl_xor_sync(0xffffffffu, l1, 1);
    l1 += __shfl_xor_sync(0xffffffffu, l1, 2);
    l2 += __shfl_xor_sync(0xffffffffu, l2, 1);
    l2 += __shfl_xor_sync(0xffffffffu, l2, 2);
    const float inv1 = 1.f / l1;
    const float inv2 = 1.f / l2;

    float* tr = reinterpret_cast<float*>(smem);    // [c][i] 64KB
#pragma unroll
    for (int cn = 0; cn < 16; ++cn) {
        const int c = cn * 8 + tig * 2;
        tr[c * 128 + r1]       = o[cn][0] * inv1;
        tr[(c + 1) * 128 + r1] = o[cn][1] * inv1;
        tr[c * 128 + r2]       = o[cn][2] * inv2;
        tr[(c + 1) * 128 + r2] = o[cn][3] * inv2;
    }
    __syncthreads();

#pragma unroll
    for (int rep = 0; rep < 16; ++rep) {
        const int lin = rep * 256 + tid;
        const int c = lin >> 5, i4 = (lin & 31) * 4;
        const float4 f = *reinterpret_cast<const float4*>(&tr[c * 128 + i4]);
        *reinterpret_cast<float4*>(&out[((size_t)n * CC + c) * HWS + i0 + i4]) = f;
    }
}

// ---------------------------------------------------------------------------
extern "C" void kernel_launch(void* const* d_in, const int* in_sizes, int n_in,
                              void* d_out, int out_size)
{
    (void)in_sizes; (void)n_in; (void)out_size;
    const float* x  = (const float*)d_in[0];
    const float* w1 = (const float*)d_in[1];
    const float* b1 = (const float*)d_in[2];
    const float* a1 = (const float*)d_in[3];
    const float* w2 = (const float*)d_in[4];
    const float* b2 = (const float*)d_in[5];
    const float* a2 = (const float*)d_in[6];
    const float* wa = (const float*)d_in[7];
    const float* ba = (const float*)d_in[8];
    const float* aa = (const float*)d_in[9];
    float* out = (float*)d_out;

    prep_kernel<<<dim3(HWS / 32, CC / 32, NB), 256>>>(x, w1, b1, a1, w2, b2, a2, wa, ba, aa);

    const int smem1 = 196608;   // 192 KB
    cudaFuncSetAttribute(proj_tc, cudaFuncAttributeMaxDynamicSharedMemorySize, smem1);
    proj_tc<<<dim3(HWS / 128, NB), 256, smem1>>>(0);

    const int smem2 = NSTAGE * STAGE_BYTES + 64;   // 144 KB + barriers
    cudaFuncSetAttribute(attn_hmma, cudaFuncAttributeMaxDynamicSharedMemorySize, smem2);
    attn_hmma<<<dim3(HWS / 128, NB), 256, smem2>>>(out);
}

// round 17
// speedup vs baseline: 1.0316x; 1.0114x over previous
#include <cuda_runtime.h>
#include <cuda_fp16.h>
#include <cstdint>

#define NB   4
#define CC   128
#define CR   64
#define HWS  4096
#define NJ   32            // j-tiles of 128
#define STAGE_BYTES 49152  // Kh 16K + Vh 32K
#define NSTAGE 3
#define PS   129           // tr stride (floats), odd -> <=2-way LDS conflicts

// ---------------------------------------------------------------------------
// Scratch
// ---------------------------------------------------------------------------
__device__ __half g_qh[NB * HWS * CR];
__device__ __half g_ql[NB * HWS * CR];
__device__ __half g_kh[NB * HWS * CR];
__device__ __half g_vh[NB * HWS * CC];
// proj_tc inputs
__device__ __half g_xh[NB * HWS * CC];   // x transposed [n][p][c], fp16 hi
__device__ __half g_xl[NB * HWS * CC];   // fp16 lo
__device__ __half g_wh[256 * 128];       // fused weights hi  [o][c]
__device__ __half g_wl[256 * 128];       // fused weights lo
__device__ float  g_bias[256];
__device__ float  g_alph[256];

// ---------------------------------------------------------------------------
// helpers
// ---------------------------------------------------------------------------
__device__ __forceinline__ uint32_t smem_u32(const void* p) {
    uint32_t a;
    asm("{ .reg .u64 t; cvta.to.shared.u64 t, %1; cvt.u32.u64 %0, t; }" : "=r"(a) : "l"(p));
    return a;
}
__device__ __forceinline__ uint32_t packh(float a, float b) {
    __half2 t = __floats2half2_rn(a, b);
    return *reinterpret_cast<uint32_t*>(&t);
}
__device__ __forceinline__ uint32_t ld32(const void* p) {
    return *reinterpret_cast<const uint32_t*>(p);
}
__device__ __forceinline__ void cpasync16(uint32_t dst, const void* src) {
    asm volatile("cp.async.cg.shared.global [%0], [%1], 16;" :: "r"(dst), "l"(src));
}
#define CP_COMMIT()   asm volatile("cp.async.commit_group;" ::: "memory")
#define CP_WAIT_ALL() asm volatile("cp.async.wait_group 0;" ::: "memory")

// mbarrier ops
#define MBAR_INIT(mb, c) asm volatile("mbarrier.init.shared.b64 [%0], %1;" :: "r"(mb), "r"(c) : "memory")
#define MBAR_ARRIVE(mb)  asm volatile("mbarrier.arrive.shared.b64 _, [%0];" :: "r"(mb) : "memory")
#define CPA_ARRIVE(mb)   asm volatile("cp.async.mbarrier.arrive.noinc.shared.b64 [%0];" :: "r"(mb) : "memory")

#define MBAR_WAIT(mb, ph) do {                                                   \
    uint32_t _m = (mb), _p = (uint32_t)(ph), _d;                                 \
    asm volatile("{ .reg .pred p; mbarrier.try_wait.parity.acquire.cta.shared::cta.b64 p, [%1], %2; selp.b32 %0,1,0,p; }" \
                 : "=r"(_d) : "r"(_m), "r"(_p) : "memory");                      \
    if (!_d) {                                                                   \
        asm volatile("{ .reg .pred P1; WL%=: mbarrier.try_wait.parity.acquire.cta.shared::cta.b64 P1, [%0], %1, 0x989680; @P1 bra.uni WD%=; bra.uni WL%=; WD%=: }" \
                     :: "r"(_m), "r"(_p) : "memory");                            \
    }                                                                            \
} while (0)

__device__ __forceinline__ void ldsm4(uint32_t& a, uint32_t& b, uint32_t& c, uint32_t& d, uint32_t addr) {
    asm volatile("ldmatrix.sync.aligned.m8n8.x4.shared.b16 {%0,%1,%2,%3}, [%4];"
                 : "=r"(a), "=r"(b), "=r"(c), "=r"(d) : "r"(addr));
}
__device__ __forceinline__ void ldsm4t(uint32_t& a, uint32_t& b, uint32_t& c, uint32_t& d, uint32_t addr) {
    asm volatile("ldmatrix.sync.aligned.m8n8.x4.trans.shared.b16 {%0,%1,%2,%3}, [%4];"
                 : "=r"(a), "=r"(b), "=r"(c), "=r"(d) : "r"(addr));
}
__device__ __forceinline__ void mma_f16(float* c, const uint32_t* a, uint32_t b0, uint32_t b1) {
    asm volatile("mma.sync.aligned.m16n8k16.row.col.f32.f16.f16.f32 "
                 "{%0,%1,%2,%3}, {%4,%5,%6,%7}, {%8,%9}, {%0,%1,%2,%3};"
                 : "+f"(c[0]), "+f"(c[1]), "+f"(c[2]), "+f"(c[3])
                 : "r"(a[0]), "r"(a[1]), "r"(a[2]), "r"(a[3]), "r"(b0), "r"(b1));
}

// ---------------------------------------------------------------------------
// Kernel P: fused prep, 64p x 64c tiles, vectorized IO.
//  grid (64, 2, 4) = 512 blocks x 256 thr.
//  blocks with (y<2, z==0) additionally convert weights: 128 blk x 256 thr
//  == 256o x 128c exactly.
// ---------------------------------------------------------------------------
__global__ __launch_bounds__(256) void prep_kernel(
    const float* __restrict__ x,
    const float* __restrict__ w1, const float* __restrict__ b1, const float* __restrict__ a1,
    const float* __restrict__ w2, const float* __restrict__ b2, const float* __restrict__ a2,
    const float* __restrict__ wa, const float* __restrict__ ba, const float* __restrict__ aa)
{
    __shared__ float t[64][65];
    const int n = blockIdx.z, c0 = blockIdx.y * 64, p0 = blockIdx.x * 64;
    const int tid = threadIdx.x;

    // ---- piggybacked weight prep ----
    if (blockIdx.z == 0 && blockIdx.y < 2) {
        const int idx = (blockIdx.y * 64 + blockIdx.x) * 256 + tid;  // 0..32767
        const int o = idx >> 7, c = idx & 127;
        const float* W; int oo; const float* bb; const float* ap;
        if (o < 64)        { W = w1; oo = o;       bb = b1; ap = a1; }
        else if (o < 128)  { W = w2; oo = o - 64;  bb = b2; ap = a2; }
        else               { W = wa; oo = o - 128; bb = ba; ap = aa; }
        const float v = W[oo * 128 + c];
        const float h = __half2float(__float2half_rn(v));
        g_wh[o * 128 + c] = __float2half_rn(h);
        g_wl[o * 128 + c] = __float2half_rn(v - h);
        if (c == 0) { g_bias[o] = bb[oo]; g_alph[o] = *ap; }
    }

    // ---- load x tile [64c][64p] with float4 ----
#pragma unroll
    for (int r = 0; r < 4; ++r) {
        const int idx = tid + 256 * r;            // 0..1023 float4 slots
        const int c_l = idx >> 4, p4 = idx & 15;
        const float4 f = *reinterpret_cast<const float4*>(
            &x[((size_t)(n * CC + c0 + c_l)) * HWS + p0 + p4 * 4]);
        t[c_l][p4 * 4]     = f.x;
        t[c_l][p4 * 4 + 1] = f.y;
        t[c_l][p4 * 4 + 2] = f.z;
        t[c_l][p4 * 4 + 3] = f.w;
    }
    __syncthreads();

    // ---- transpose + hi/lo convert, 16B stores (8 c per thread) ----
#pragma unroll
    for (int r = 0; r < 2; ++r) {
        const int idx = tid + 256 * r;            // 0..511
        const int p = idx >> 3, g8 = idx & 7;     // p 0..63, 8-c granule
        uint32_t hv[4], lv[4];
#pragma unroll
        for (int e = 0; e < 4; ++e) {
            const float v0 = t[g8 * 8 + e * 2][p];
            const float v1 = t[g8 * 8 + e * 2 + 1][p];
            const float h0 = __half2float(__float2half_rn(v0));
            const float h1 = __half2float(__float2half_rn(v1));
            hv[e] = packh(h0, h1);
            lv[e] = packh(v0 - h0, v1 - h1);
        }
        const size_t off = ((size_t)(n * HWS + p0 + p)) * CC + c0 + g8 * 8;
        *reinterpret_cast<uint4*>(&g_xh[off]) = make_uint4(hv[0], hv[1], hv[2], hv[3]);
        *reinterpret_cast<uint4*>(&g_xl[off]) = make_uint4(lv[0], lv[1], lv[2], lv[3]);
    }
}

// ---------------------------------------------------------------------------
// Kernel C: tensor-core proj GEMM (3-pass hi/lo) + bias + PReLU -> scratch.
// CTA: 256 thr / 8 warps, output 256o x 128p.  grid (32, NB) = 1 wave.
// ---------------------------------------------------------------------------
__global__ __launch_bounds__(256, 1) void proj_tc(int dummy)
{
    extern __shared__ char smem[];
    const uint32_t sb = smem_u32(smem);
    const uint32_t WHs = sb, WLs = sb + 65536, XHs = sb + 131072, XLs = sb + 163840;

    const int n  = blockIdx.y;
    const int p0 = blockIdx.x * 128;
    const int tid = threadIdx.x;
    const int w = tid >> 5, lane = tid & 31;

    // ---- load W (hi/lo) and x tile (hi/lo) into swizzled smem ----
    {
        const char* wh = reinterpret_cast<const char*>(g_wh);
        const char* wl = reinterpret_cast<const char*>(g_wl);
        const char* xh = reinterpret_cast<const char*>(g_xh) + ((size_t)(n * HWS + p0)) * CC * 2;
        const char* xl = reinterpret_cast<const char*>(g_xl) + ((size_t)(n * HWS + p0)) * CC * 2;
#pragma unroll
        for (int r = 0; r < 16; ++r) {
            const int idx = tid + 256 * r;        // 0..4095
            const int o = idx >> 4, gq = idx & 15;
            const int dst = o * 256 + (((gq ^ (o & 7))) << 4);
            cpasync16(WHs + dst, wh + o * 256 + gq * 16);
            cpasync16(WLs + dst, wl + o * 256 + gq * 16);
        }
#pragma unroll
        for (int r = 0; r < 8; ++r) {
            const int idx = tid + 256 * r;        // 0..2047
            const int p = idx >> 4, gq = idx & 15;
            const int dst = p * 256 + (((gq ^ (p & 7))) << 4);
            cpasync16(XHs + dst, xh + p * 256 + gq * 16);
            cpasync16(XLs + dst, xl + p * 256 + gq * 16);
        }
    }
    CP_COMMIT();
    CP_WAIT_ALL();
    __syncthreads();

    // ---- GEMM: warp m32 x n128 over K=128, 3 passes (Wh*xh + Wh*xl + Wl*xh)
    float acc[2][16][4];
#pragma unroll
    for (int mh = 0; mh < 2; ++mh)
#pragma unroll
        for (int nc = 0; nc < 16; ++nc)
#pragma unroll
            for (int q = 0; q < 4; ++q) acc[mh][nc][q] = 0.f;

#pragma unroll
    for (int ks = 0; ks < 8; ++ks) {
        uint32_t ah[2][4], al[2][4];
#pragma unroll
        for (int mh = 0; mh < 2; ++mh) {
            const int row = w * 32 + mh * 16 + (lane & 15);
            const int gq = ks * 2 + (lane >> 4);
            const uint32_t ad = WHs + row * 256 + (((gq ^ (row & 7))) << 4);
            ldsm4(ah[mh][0], ah[mh][1], ah[mh][2], ah[mh][3], ad);
            ldsm4(al[mh][0], al[mh][1], al[mh][2], al[mh][3], ad + 65536);
        }
#pragma unroll
        for (int nc = 0; nc < 8; ++nc) {
            const int j = nc * 16 + ((lane >> 4) & 1) * 8 + (lane & 7);
            const int gq = ks * 2 + ((lane >> 3) & 1);
            const uint32_t ad = XHs + j * 256 + (((gq ^ (j & 7))) << 4);
            uint32_t b0, b1, b2, b3;
            ldsm4(b0, b1, b2, b3, ad);           // xh
            uint32_t c0, c1, c2, c3;
            ldsm4(c0, c1, c2, c3, ad + 32768);   // xl
#pragma unroll
            for (int mh = 0; mh < 2; ++mh) {
                mma_f16(acc[mh][2 * nc],     ah[mh], b0, b1);
                mma_f16(acc[mh][2 * nc + 1], ah[mh], b2, b3);
                mma_f16(acc[mh][2 * nc],     ah[mh], c0, c1);
                mma_f16(acc[mh][2 * nc + 1], ah[mh], c2, c3);
                mma_f16(acc[mh][2 * nc],     al[mh], b0, b1);
                mma_f16(acc[mh][2 * nc + 1], al[mh], b2, b3);
            }
        }
    }
    __syncthreads();   // done reading W/X smem

    // ---- bias + PReLU -> fp32 transpose buffer tr[o][PS] ----
    float* tr = reinterpret_cast<float*>(smem);
#pragma unroll
    for (int mh = 0; mh < 2; ++mh) {
        const int o1 = w * 32 + mh * 16 + (lane >> 2);
        const int o2 = o1 + 8;
        const float bi1 = g_bias[o1], al1 = g_alph[o1];
        const float bi2 = g_bias[o2], al2 = g_alph[o2];
#pragma unroll
        for (int t = 0; t < 16; ++t) {
            const int p = t * 8 + (lane & 3) * 2;
            float v0 = acc[mh][t][0] + bi1;
            float v1 = acc[mh][t][1] + bi1;
            float v2 = acc[mh][t][2] + bi2;
            float v3 = acc[mh][t][3] + bi2;
            v0 = (v0 >= 0.f) ? v0 : al1 * v0;
            v1 = (v1 >= 0.f) ? v1 : al1 * v1;
            v2 = (v2 >= 0.f) ? v2 : al2 * v2;
            v3 = (v3 >= 0.f) ? v3 : al2 * v3;
            tr[o1 * PS + p] = v0; tr[o1 * PS + p + 1] = v1;
            tr[o2 * PS + p] = v2; tr[o2 * PS + p + 1] = v3;
        }
    }
    __syncthreads();

    // ---- pack to scratch ----
#pragma unroll
    for (int r = 0; r < 16; ++r) {
        const int pair = tid + 256 * r;           // 0..4095
        const int p = pair >> 5, op = (pair & 31) * 2;
        const float v0 = tr[op * PS + p], v1 = tr[(op + 1) * PS + p];
        const float h0 = __half2float(__float2half_rn(v0));
        const float h1 = __half2float(__float2half_rn(v1));
        const size_t off = ((size_t)(n * HWS + p0 + p)) * CR + op;
        *reinterpret_cast<uint32_t*>(&g_qh[off]) = packh(h0, h1);
        *reinterpret_cast<uint32_t*>(&g_ql[off]) = packh(v0 - h0, v1 - h1);
    }
#pragma unroll
    for (int r = 0; r < 16; ++r) {
        const int pair = tid + 256 * r;
        const int p = pair >> 5, op = 64 + (pair & 31) * 2;
        const size_t off = ((size_t)(n * HWS + p0 + p)) * CR + op - 64;
        *reinterpret_cast<uint32_t*>(&g_kh[off]) =
            packh(tr[op * PS + p], tr[(op + 1) * PS + p]);
    }
#pragma unroll
    for (int r = 0; r < 32; ++r) {
        const int pair = tid + 256 * r;           // 0..8191
        const int p = pair >> 6, cp = pair & 63;
        const int op = 128 + cp * 2;
        const size_t off = ((size_t)(n * HWS + p0 + p)) * CC + cp * 2;
        *reinterpret_cast<uint32_t*>(&g_vh[off]) =
            packh(tr[op * PS + p], tr[(op + 1) * PS + p]);
    }
    (void)dummy;
}

// ---------------------------------------------------------------------------
// attn stage loader: Kh (16K) + V (32K) tiles, XOR-swizzled, via cp.async
// ---------------------------------------------------------------------------
__device__ __forceinline__ void load_tile(uint32_t stage, int n, int jt, int tid) {
    const char* kh = reinterpret_cast<const char*>(g_kh) + ((size_t)(n * HWS + jt * 128)) * CR * 2;
    const char* vh = reinterpret_cast<const char*>(g_vh) + ((size_t)(n * HWS + jt * 128)) * CC * 2;
#pragma unroll
    for (int r = 0; r < 4; ++r) {
        const int idx = tid + 256 * r;            // 0..1023
        const int j = idx >> 3, g = idx & 7;
        const int dstoff = j * 128 + (((g ^ (j & 7))) << 4);
        cpasync16(stage + dstoff, kh + j * 128 + g * 16);
    }
#pragma unroll
    for (int r = 0; r < 8; ++r) {
        const int idx = tid + 256 * r;            // 0..2047
        const int j = idx >> 4, g = idx & 15;
        const int dstoff = j * 256 + (((g ^ (j & 7))) << 4);
        cpasync16(stage + 16384 + dstoff, vh + j * 256 + g * 16);
    }
}

// ---------------------------------------------------------------------------
// Kernel 2: flash attention (R13-exact body, best measured: 112.4us).
// QK: A-side fp16 hi/lo 2-pass (exact Q), K single fp16.  PV: fp16 1-pass.
// ---------------------------------------------------------------------------
__global__ __launch_bounds__(256, 1) void attn_hmma(float* __restrict__ out)
{
    extern __shared__ char smem[];
    const uint32_t sb  = smem_u32(smem);
    const uint32_t BAR = sb + NSTAGE * STAGE_BYTES;   // 6 mbarriers

    const int n   = blockIdx.y;
    const int i0  = blockIdx.x * 128;
    const int tid = threadIdx.x;
    const int w = tid >> 5, lane = tid & 31;
    const int g = lane >> 2, tig = lane & 3;
    const int r1 = w * 16 + g, r2 = r1 + 8;

    if (tid == 0) {
#pragma unroll
        for (int s = 0; s < NSTAGE; ++s) {
            MBAR_INIT(BAR + s * 8, 256);              // full[s]
            MBAR_INIT(BAR + 24 + s * 8, 256);         // empty[s]
        }
    }
    __syncthreads();

    // ---- Q fragments (persistent, fp16 hi/lo) ----
    uint32_t qh[4][4], ql[4][4];
    {
        const __half* q1h = g_qh + ((size_t)(n * HWS + i0 + r1)) * CR + tig * 2;
        const __half* q2h = g_qh + ((size_t)(n * HWS + i0 + r2)) * CR + tig * 2;
        const __half* q1l = g_ql + ((size_t)(n * HWS + i0 + r1)) * CR + tig * 2;
        const __half* q2l = g_ql + ((size_t)(n * HWS + i0 + r2)) * CR + tig * 2;
#pragma unroll
        for (int ks = 0; ks < 4; ++ks) {
            qh[ks][0] = ld32(q1h + ks * 16);     qh[ks][1] = ld32(q2h + ks * 16);
            qh[ks][2] = ld32(q1h + ks * 16 + 8); qh[ks][3] = ld32(q2h + ks * 16 + 8);
            ql[ks][0] = ld32(q1l + ks * 16);     ql[ks][1] = ld32(q2l + ks * 16);
            ql[ks][2] = ld32(q1l + ks * 16 + 8); ql[ks][3] = ld32(q2l + ks * 16 + 8);
        }
    }

    float m1 = -1e30f, m2 = -1e30f, l1 = 0.f, l2 = 0.f;

    float o[16][4];
#pragma unroll
    for (int cn = 0; cn < 16; ++cn)
#pragma unroll
        for (int q = 0; q < 4; ++q) o[cn][q] = 0.f;

    // prologue: stages 0 and 1
    load_tile(sb,               n, 0, tid);  CPA_ARRIVE(BAR);
    load_tile(sb + STAGE_BYTES, n, 1, tid);  CPA_ARRIVE(BAR + 8);

    int sc_ = 0, fpar = 0, fcnt = 0;     // consumer stage + full parity
    int sp_ = 2, epar = 0, ecnt = 0;     // producer stage + empty parity

    for (int jt = 0; jt < NJ; ++jt) {
        const int jt2 = jt + 2;
        if (jt2 < NJ) {
            if (jt2 >= NSTAGE) {
                MBAR_WAIT(BAR + 24 + sp_ * 8, epar);
                if (++ecnt == NSTAGE) { ecnt = 0; epar ^= 1; }
            }
            load_tile(sb + sp_ * STAGE_BYTES, n, jt2, tid);
            CPA_ARRIVE(BAR + sp_ * 8);
            if (++sp_ == NSTAGE) sp_ = 0;
        }

        MBAR_WAIT(BAR + sc_ * 8, fpar);
        if (++fcnt == NSTAGE) { fcnt = 0; fpar ^= 1; }

        const uint32_t KHs = sb + sc_ * STAGE_BYTES;
        const uint32_t VHs = KHs + 16384;

        // ---- QK: S = (Qh + Ql) * Kh  (fp16 A-split 2-pass, exact in Q) ----
        float s[16][4];
#pragma unroll
        for (int jn = 0; jn < 16; ++jn)
#pragma unroll
            for (int q = 0; q < 4; ++q) s[jn][q] = 0.f;

#pragma unroll
        for (int ks = 0; ks < 4; ++ks) {
#pragma unroll
            for (int jnp = 0; jnp < 8; ++jnp) {
                const int j = jnp * 16 + ((lane >> 4) & 1) * 8 + (lane & 7);
                const int gr = ks * 2 + ((lane >> 3) & 1);
                const uint32_t ad = KHs + j * 128 + (((gr) ^ (j & 7)) << 4);
                uint32_t b0, b1, b2, b3;
                ldsm4(b0, b1, b2, b3, ad);
                mma_f16(s[2 * jnp],     qh[ks], b0, b1);
                mma_f16(s[2 * jnp + 1], qh[ks], b2, b3);
                mma_f16(s[2 * jnp],     ql[ks], b0, b1);
                mma_f16(s[2 * jnp + 1], ql[ks], b2, b3);
            }
        }

        // ---- online softmax: true row max (quad-reduced), rescale O ----
        float mx1 = -1e30f, mx2 = -1e30f;
#pragma unroll
        for (int jn = 0; jn < 16; ++jn) {
            mx1 = fmaxf(mx1, fmaxf(s[jn][0], s[jn][1]));
            mx2 = fmaxf(mx2, fmaxf(s[jn][2], s[jn][3]));
        }
        mx1 = fmaxf(mx1, __shfl_xor_sync(0xffffffffu, mx1, 1));
        mx1 = fmaxf(mx1, __shfl_xor_sync(0xffffffffu, mx1, 2));
        mx2 = fmaxf(mx2, __shfl_xor_sync(0xffffffffu, mx2, 1));
        mx2 = fmaxf(mx2, __shfl_xor_sync(0xffffffffu, mx2, 2));
        const float mn1 = fmaxf(m1, mx1), mn2 = fmaxf(m2, mx2);
        const float sc1 = __expf(m1 - mn1), sc2 = __expf(m2 - mn2);
        m1 = mn1; m2 = mn2;
        l1 *= sc1; l2 *= sc2;
#pragma unroll
        for (int cn = 0; cn < 16; ++cn) {
            o[cn][0] *= sc1; o[cn][1] *= sc1;
            o[cn][2] *= sc2; o[cn][3] *= sc2;
        }

        uint32_t ph[16][2];
#pragma unroll
        for (int jn = 0; jn < 16; ++jn) {
            const float p0 = __expf(s[jn][0] - mn1);
            const float p1 = __expf(s[jn][1] - mn1);
            const float p2 = __expf(s[jn][2] - mn2);
            const float p3 = __expf(s[jn][3] - mn2);
            l1 += p0 + p1;
            l2 += p2 + p3;
            ph[jn][0] = packh(p0, p1);
            ph[jn][1] = packh(p2, p3);
        }

        // ---- PV: O += P*V (single fp16 pass) ----
#pragma unroll
        for (int t = 0; t < 8; ++t) {
            const uint32_t a[4] = {ph[2 * t][0], ph[2 * t][1], ph[2 * t + 1][0], ph[2 * t + 1][1]};
#pragma unroll
            for (int cnp = 0; cnp < 8; ++cnp) {
                const int j = t * 16 + ((lane >> 3) & 1) * 8 + (lane & 7);
                const int gr = cnp * 2 + ((lane >> 4) & 1);
                const uint32_t ad = VHs + j * 256 + (((gr) ^ (j & 7)) << 4);
                uint32_t b0, b1, b2, b3;
                ldsm4t(b0, b1, b2, b3, ad);
                mma_f16(o[2 * cnp],     a, b0, b1);
                mma_f16(o[2 * cnp + 1], a, b2, b3);
            }
        }

        MBAR_ARRIVE(BAR + 24 + sc_ * 8);
        if (++sc_ == NSTAGE) sc_ = 0;
    }

    __syncthreads();   // all warps done before tr reuses stage 0

    // ---- epilogue: reduce l over quad, normalize, transpose, store ----
    l1 += __shfl_xor_sync(0xffffffffu, l1, 1);
    l1 += __shfl_xor_sync(0xffffffffu, l1, 2);
    l2 += __shfl_xor_sync(0xffffffffu, l2, 1);
    l2 += __shfl_xor_sync(0xffffffffu, l2, 2);
    const float inv1 = 1.f / l1;
    const float inv2 = 1.f / l2;

    float* tr = reinterpret_cast<float*>(smem);    // [c][i] 64KB
#pragma unroll
    for (int cn = 0; cn < 16; ++cn) {
        const int c = cn * 8 + tig * 2;
        tr[c * 128 + r1]       = o[cn][0] * inv1;
        tr[(c + 1) * 128 + r1] = o[cn][1] * inv1;
        tr[c * 128 + r2]       = o[cn][2] * inv2;
        tr[(c + 1) * 128 + r2] = o[cn][3] * inv2;
    }
    __syncthreads();

#pragma unroll
    for (int rep = 0; rep < 16; ++rep) {
        const int lin = rep * 256 + tid;
        const int c = lin >> 5, i4 = (lin & 31) * 4;
        const float4 f = *reinterpret_cast<const float4*>(&tr[c * 128 + i4]);
        *reinterpret_cast<float4*>(&out[((size_t)n * CC + c) * HWS + i0 + i4]) = f;
    }
}

// ---------------------------------------------------------------------------
extern "C" void kernel_launch(void* const* d_in, const int* in_sizes, int n_in,
                              void* d_out, int out_size)
{
    (void)in_sizes; (void)n_in; (void)out_size;
    const float* x  = (const float*)d_in[0];
    const float* w1 = (const float*)d_in[1];
    const float* b1 = (const float*)d_in[2];
    const float* a1 = (const float*)d_in[3];
    const float* w2 = (const float*)d_in[4];
    const float* b2 = (const float*)d_in[5];
    const float* a2 = (const float*)d_in[6];
    const float* wa = (const float*)d_in[7];
    const float* ba = (const float*)d_in[8];
    const float* aa = (const float*)d_in[9];
    float* out = (float*)d_out;

    prep_kernel<<<dim3(HWS / 64, CC / 64, NB), 256>>>(x, w1, b1, a1, w2, b2, a2, wa, ba, aa);

    const int smem1 = 196608;   // 192 KB
    cudaFuncSetAttribute(proj_tc, cudaFuncAttributeMaxDynamicSharedMemorySize, smem1);
    proj_tc<<<dim3(HWS / 128, NB), 256, smem1>>>(0);

    const int smem2 = NSTAGE * STAGE_BYTES + 64;   // 144 KB + barriers
    cudaFuncSetAttribute(attn_hmma, cudaFuncAttributeMaxDynamicSharedMemorySize, smem2);
    attn_hmma<<<dim3(HWS / 128, NB), 256, smem2>>>(out);
}